// round 15
// baseline (speedup 1.0000x reference)
#include <cuda_runtime.h>
#include <math.h>
#include <stdint.h>

#define NN 50000
#define NE 1000000
#define NI 200000
#define NB 5000
#define H  128

#define SCAN_NBLK ((NN + 255) / 256)   // 196

// ---------------- scratch (device globals; no runtime alloc) ----------------
__device__ float g_A[NN * H];
__device__ float g_B[NN * H];
__device__ float g_L[NN * H];
__device__ float g_R[NN * H];
__device__ int   g_deg[NN];
__device__ int   g_off[NN + 1];
__device__ int   g_cur[NN];
__device__ int   g_csr[NE];
__device__ int   g_bsum[SCAN_NBLK];
__device__ int   g_bpre[SCAN_NBLK];
// pre-converted weight fragment planes: 14 matrices x (8192 hi + 8192 lo) words
__device__ uint32_t g_Wf[14 * 16384];

// ---------------- small utility kernels ----------------
__global__ void zero_deg_kernel() {
    int i = blockIdx.x * blockDim.x + threadIdx.x;
    if (i < NN) g_deg[i] = 0;
}

__global__ void count_deg_kernel(const int* __restrict__ dst) {
    int e = blockIdx.x * blockDim.x + threadIdx.x;
    if (e < NE) atomicAdd(&g_deg[dst[e]], 1);
}

// ---- 3-phase multi-block exclusive scan of g_deg -> g_off/g_cur ----
__global__ void scan1_kernel() {
    __shared__ int ts[256];
    int b = blockIdx.x, tid = threadIdx.x;
    int idx = b * 256 + tid;
    int d = (idx < NN) ? g_deg[idx] : 0;
    ts[tid] = d;
    __syncthreads();
#pragma unroll
    for (int o = 1; o < 256; o <<= 1) {
        int t = (tid >= o) ? ts[tid - o] : 0;
        __syncthreads();
        ts[tid] += t;
        __syncthreads();
    }
    if (idx < NN) g_off[idx] = ts[tid] - d;   // local exclusive prefix
    if (tid == 255) g_bsum[b] = ts[255];
}

__global__ void scan2_kernel() {
    __shared__ int ts[256];
    int tid = threadIdx.x;
    int v = (tid < SCAN_NBLK) ? g_bsum[tid] : 0;
    ts[tid] = v;
    __syncthreads();
#pragma unroll
    for (int o = 1; o < 256; o <<= 1) {
        int t = (tid >= o) ? ts[tid - o] : 0;
        __syncthreads();
        ts[tid] += t;
        __syncthreads();
    }
    if (tid < SCAN_NBLK) g_bpre[tid] = ts[tid] - v;   // exclusive block offset
    if (tid == SCAN_NBLK - 1) g_off[NN] = ts[tid];
}

__global__ void scan3_kernel() {
    int b = blockIdx.x, tid = threadIdx.x;
    int idx = b * 256 + tid;
    if (idx < NN) {
        int o = g_off[idx] + g_bpre[b];
        g_off[idx] = o;
        g_cur[idx] = o;
    }
}

__global__ void scatter_kernel(const int* __restrict__ src, const int* __restrict__ dst) {
    int e = blockIdx.x * blockDim.x + threadIdx.x;
    if (e < NE) {
        int d = dst[e];
        int p = atomicAdd(&g_cur[d], 1);
        g_csr[p] = src[e];
    }
}

// ---------------- bf16 split helpers ----------------
__device__ __forceinline__ uint32_t bf16x2_trunc(float x0, float x1) {
    uint32_t r;
    asm("prmt.b32 %0, %1, %2, 0x7632;" : "=r"(r)
        : "r"(__float_as_uint(x0)), "r"(__float_as_uint(x1)));
    return r;
}
__device__ __forceinline__ float bf_hi(float x) {
    return __uint_as_float(__float_as_uint(x) & 0xFFFF0000u);
}
__device__ __forceinline__ uint32_t bf16x2_rn(float x0, float x1) {
    uint32_t r;
    asm("cvt.rn.bf16x2.f32 %0, %1, %2;" : "=r"(r) : "f"(x1), "f"(x0));
    return r;
}

__device__ __forceinline__ void mma_bf16(float* d, const uint32_t* a, const uint32_t* b) {
    asm volatile(
        "mma.sync.aligned.m16n8k16.row.col.f32.bf16.bf16.f32 "
        "{%0,%1,%2,%3}, {%4,%5,%6,%7}, {%8,%9}, {%0,%1,%2,%3};\n"
        : "+f"(d[0]), "+f"(d[1]), "+f"(d[2]), "+f"(d[3])
        : "r"(a[0]), "r"(a[1]), "r"(a[2]), "r"(a[3]), "r"(b[0]), "r"(b[1]));
}

// ---------------- weight prep: convert 14 matrices to fragment planes ----------------
__global__ __launch_bounds__(256)
void prep_weights(const float* __restrict__ encW, const float* __restrict__ gWl,
                  const float* __restrict__ gWr, const float* __restrict__ eW0,
                  const float* __restrict__ eW1, const float* __restrict__ nW0,
                  const float* __restrict__ nW1) {
    int b = blockIdx.x;
    const float* W;
    if (b < 3)       W = encW + b * 16384;
    else if (b < 6)  W = gWl + (b - 3) * 16384;
    else if (b < 9)  W = gWr + (b - 6) * 16384;
    else if (b == 9) W = eW0;
    else if (b == 10) W = eW0 + 16384;
    else if (b == 11) W = eW1;
    else if (b == 12) W = nW0;
    else             W = nW1;
    uint32_t* dstH = g_Wf + b * 16384;
    uint32_t* dstL = dstH + 8192;

    int tid = threadIdx.x;
    int warp = tid >> 5, lane = tid & 31, g = lane >> 2, tg = lane & 3;
#pragma unroll
    for (int h = 0; h < 2; h++) {
        int cbi = warp * 2 + h;
        const float* Wc = W + cbi * 8 + g;
#pragma unroll 2
        for (int k16i = 0; k16i < 8; k16i++) {
            int k = k16i * 16 + 2 * tg;
            float w0 = Wc[(size_t)k * 128];
            float w1 = Wc[(size_t)(k + 1) * 128];
            float w8 = Wc[(size_t)(k + 8) * 128];
            float w9 = Wc[(size_t)(k + 9) * 128];
            uint32_t b0h = bf16x2_trunc(w0, w1);
            uint32_t b1h = bf16x2_trunc(w8, w9);
            uint32_t b0l = bf16x2_rn(w0 - bf_hi(w0), w1 - bf_hi(w1));
            uint32_t b1l = bf16x2_rn(w8 - bf_hi(w8), w9 - bf_hi(w9));
            int fi = ((k16i * 8 + warp) * 32 + lane) * 4 + h * 2;
            *reinterpret_cast<uint2*>(dstH + fi) = make_uint2(b0h, b1h);
            *reinterpret_cast<uint2*>(dstL + fi) = make_uint2(b0l, b1l);
        }
    }
}

// SMEM planes (uint32 words):
//   AfH/AfL: [rbi(8)][k16i(8)][lane(32)][4] = 8192 words each
//   BfH/BfL: [k16i(8)][cbj(8)][lane(32)][4] = 8192 words each (paired cbi)
#define MMA_SMEM_BYTES (32768 * 4)
#define CS_P 132

__device__ __forceinline__ void copy_Wfrag(uint32_t* BfH, const uint32_t* __restrict__ Wf,
                                           int tid) {
    const uint4* s = reinterpret_cast<const uint4*>(Wf);
    uint4* d = reinterpret_cast<uint4*>(BfH);
#pragma unroll 4
    for (int i = tid; i < 4096; i += 256) d[i] = s[i];
}

__device__ __forceinline__ void mma_mainloop(const uint32_t* AfH, const uint32_t* AfL,
                                             const uint32_t* BfH, const uint32_t* BfL,
                                             int wr, int wc, int lane,
                                             float acc[2][8][4]) {
#pragma unroll
    for (int i = 0; i < 2; i++)
#pragma unroll
        for (int j = 0; j < 8; j++)
#pragma unroll
            for (int c = 0; c < 4; c++) acc[i][j][c] = 0.f;

#pragma unroll 2
    for (int k16i = 0; k16i < 8; k16i++) {
        uint4 ah[2], al[2];
#pragma unroll
        for (int i = 0; i < 2; i++) {
            int fi = (((wr * 2 + i) * 8 + k16i) * 32 + lane) * 4;
            ah[i] = *reinterpret_cast<const uint4*>(AfH + fi);
            al[i] = *reinterpret_cast<const uint4*>(AfL + fi);
        }
        uint4 bh[4], bl[4];
#pragma unroll
        for (int p = 0; p < 4; p++) {
            int fi = ((k16i * 8 + wc * 4 + p) * 32 + lane) * 4;
            bh[p] = *reinterpret_cast<const uint4*>(BfH + fi);
            bl[p] = *reinterpret_cast<const uint4*>(BfL + fi);
        }
#pragma unroll
        for (int i = 0; i < 2; i++) {
            uint32_t aH[4] = {ah[i].x, ah[i].y, ah[i].z, ah[i].w};
            uint32_t aL[4] = {al[i].x, al[i].y, al[i].z, al[i].w};
#pragma unroll
            for (int p = 0; p < 4; p++) {
                uint32_t bH0[2] = {bh[p].x, bh[p].y};
                uint32_t bH1[2] = {bh[p].z, bh[p].w};
                uint32_t bL0[2] = {bl[p].x, bl[p].y};
                uint32_t bL1[2] = {bl[p].z, bl[p].w};
                mma_bf16(acc[i][2 * p + 0], aH, bH0);
                mma_bf16(acc[i][2 * p + 0], aH, bL0);
                mma_bf16(acc[i][2 * p + 0], aL, bH0);
                mma_bf16(acc[i][2 * p + 1], aH, bH1);
                mma_bf16(acc[i][2 * p + 1], aH, bL1);
                mma_bf16(acc[i][2 * p + 1], aL, bH1);
            }
        }
    }
}

__device__ __forceinline__ void mma_epi_store(float acc[2][8][4], int m0, int M,
                                              int wr, int wc, int g, int tg,
                                              const float* __restrict__ bias, int relu,
                                              float* __restrict__ C) {
    int rA0 = wr * 32, cB0 = wc * 64;
#pragma unroll
    for (int i = 0; i < 2; i++) {
#pragma unroll
        for (int hh = 0; hh < 2; hh++) {
            int gr = m0 + rA0 + i * 16 + g + hh * 8;
            if (gr < M) {
#pragma unroll
                for (int j = 0; j < 8; j++) {
                    int col = cB0 + j * 8 + 2 * tg;
                    float b0v = bias ? bias[col] : 0.f;
                    float b1v = bias ? bias[col + 1] : 0.f;
                    float2 o;
                    o.x = acc[i][j][hh * 2 + 0] + b0v;
                    o.y = acc[i][j][hh * 2 + 1] + b1v;
                    if (relu) { o.x = fmaxf(o.x, 0.f); o.y = fmaxf(o.y, 0.f); }
                    *reinterpret_cast<float2*>(C + (size_t)gr * 128 + col) = o;
                }
            }
        }
    }
}

// ---------------- split-bf16 GEMM: C[M,128] = epi(A[M,128] @ W + b) ----------------
// MODE_A: 0=plain, 1=gather idx0, 2=relu(Ha[idx0]+Hb[idx1]), 3=concat(x[64]|emb[64])
// MODE_E: 0=bias, 1=bias+relu, 2=fused relu->dot(w2)+b2->sigmoid->outv
template <int MODE_A, int MODE_E>
__global__ __launch_bounds__(256, 1)
void mma_gemm(const float* __restrict__ A, const float* __restrict__ A2,
              const int* __restrict__ idx0, const int* __restrict__ idx1,
              int M, const uint32_t* __restrict__ Wf, const float* __restrict__ bias,
              float* __restrict__ C, const float* __restrict__ w2,
              const float* __restrict__ b2, float* __restrict__ outv) {
    extern __shared__ uint32_t smem_u[];
    uint32_t* AfH = smem_u;
    uint32_t* AfL = smem_u + 8192;
    uint32_t* BfH = smem_u + 16384;
    uint32_t* BfL = smem_u + 24576;

    int tid = threadIdx.x;
    int m0 = blockIdx.x * 128;
    int warp = tid >> 5, lane = tid & 31;
    int g = lane >> 2, tg = lane & 3;

    copy_Wfrag(BfH, Wf, tid);

    // ---- stage A hi/lo fragments: rbi = warp, rows r1 = m0+warp*16+g, r2 = r1+8 ----
    {
        int r1 = m0 + warp * 16 + g;
        int r2 = r1 + 8;
        bool ok1 = r1 < M, ok2 = r2 < M;
        const float *p1 = nullptr, *p2 = nullptr, *q1 = nullptr, *q2 = nullptr;
        if constexpr (MODE_A == 0) {
            if (ok1) p1 = A + (size_t)r1 * H;
            if (ok2) p2 = A + (size_t)r2 * H;
        } else if constexpr (MODE_A == 1) {
            if (ok1) p1 = A + (size_t)idx0[r1] * H;
            if (ok2) p2 = A + (size_t)idx0[r2] * H;
        } else if constexpr (MODE_A == 2) {
            if (ok1) { p1 = A + (size_t)idx0[r1] * H; q1 = A2 + (size_t)idx1[r1] * H; }
            if (ok2) { p2 = A + (size_t)idx0[r2] * H; q2 = A2 + (size_t)idx1[r2] * H; }
        }
#pragma unroll 2
        for (int k16i = 0; k16i < 8; k16i++) {
            int k = k16i * 16 + 2 * tg;
            float2 v0a = make_float2(0.f, 0.f), v0b = v0a, v1a = v0a, v1b = v0a;
            if constexpr (MODE_A == 3) {
                int kk = (k16i < 4) ? k : (k - 64);
                const float* s = (k16i < 4) ? A : A2;
                if (ok1) {
                    v0a = *reinterpret_cast<const float2*>(s + (size_t)r1 * 64 + kk);
                    v0b = *reinterpret_cast<const float2*>(s + (size_t)r1 * 64 + kk + 8);
                }
                if (ok2) {
                    v1a = *reinterpret_cast<const float2*>(s + (size_t)r2 * 64 + kk);
                    v1b = *reinterpret_cast<const float2*>(s + (size_t)r2 * 64 + kk + 8);
                }
            } else if constexpr (MODE_A == 2) {
                if (p1) {
                    float2 a0 = *reinterpret_cast<const float2*>(p1 + k);
                    float2 b0 = *reinterpret_cast<const float2*>(q1 + k);
                    float2 a8 = *reinterpret_cast<const float2*>(p1 + k + 8);
                    float2 b8 = *reinterpret_cast<const float2*>(q1 + k + 8);
                    v0a = make_float2(fmaxf(a0.x + b0.x, 0.f), fmaxf(a0.y + b0.y, 0.f));
                    v0b = make_float2(fmaxf(a8.x + b8.x, 0.f), fmaxf(a8.y + b8.y, 0.f));
                }
                if (p2) {
                    float2 a0 = *reinterpret_cast<const float2*>(p2 + k);
                    float2 b0 = *reinterpret_cast<const float2*>(q2 + k);
                    float2 a8 = *reinterpret_cast<const float2*>(p2 + k + 8);
                    float2 b8 = *reinterpret_cast<const float2*>(q2 + k + 8);
                    v1a = make_float2(fmaxf(a0.x + b0.x, 0.f), fmaxf(a0.y + b0.y, 0.f));
                    v1b = make_float2(fmaxf(a8.x + b8.x, 0.f), fmaxf(a8.y + b8.y, 0.f));
                }
            } else {
                if (p1) {
                    v0a = *reinterpret_cast<const float2*>(p1 + k);
                    v0b = *reinterpret_cast<const float2*>(p1 + k + 8);
                }
                if (p2) {
                    v1a = *reinterpret_cast<const float2*>(p2 + k);
                    v1b = *reinterpret_cast<const float2*>(p2 + k + 8);
                }
            }
            uint32_t a0h = bf16x2_trunc(v0a.x, v0a.y);
            uint32_t a1h = bf16x2_trunc(v1a.x, v1a.y);
            uint32_t a2h = bf16x2_trunc(v0b.x, v0b.y);
            uint32_t a3h = bf16x2_trunc(v1b.x, v1b.y);
            uint32_t a0l = bf16x2_rn(v0a.x - bf_hi(v0a.x), v0a.y - bf_hi(v0a.y));
            uint32_t a1l = bf16x2_rn(v1a.x - bf_hi(v1a.x), v1a.y - bf_hi(v1a.y));
            uint32_t a2l = bf16x2_rn(v0b.x - bf_hi(v0b.x), v0b.y - bf_hi(v0b.y));
            uint32_t a3l = bf16x2_rn(v1b.x - bf_hi(v1b.x), v1b.y - bf_hi(v1b.y));
            int fi = ((warp * 8 + k16i) * 32 + lane) * 4;
            *reinterpret_cast<uint4*>(AfH + fi) = make_uint4(a0h, a1h, a2h, a3h);
            *reinterpret_cast<uint4*>(AfL + fi) = make_uint4(a0l, a1l, a2l, a3l);
        }
    }
    __syncthreads();

    int wr = warp >> 1, wc = warp & 1;
    float acc[2][8][4];
    mma_mainloop(AfH, AfL, BfH, BfL, wr, wc, lane, acc);

    if constexpr (MODE_E < 2) {
        mma_epi_store(acc, m0, M, wr, wc, g, tg, bias, MODE_E == 1, C);
    } else {
        // fused tail: relu(acc + b1) -> Cs(smem) -> dot(w2)+b2 -> sigmoid
        __syncthreads();
        float* Cs = reinterpret_cast<float*>(smem_u);
        int rA0 = wr * 32, cB0 = wc * 64;
#pragma unroll
        for (int i = 0; i < 2; i++) {
#pragma unroll
            for (int hh = 0; hh < 2; hh++) {
                int rr = rA0 + i * 16 + g + hh * 8;
#pragma unroll
                for (int j = 0; j < 8; j++) {
                    int col = cB0 + j * 8 + 2 * tg;
                    float2 o;
                    o.x = fmaxf(acc[i][j][hh * 2 + 0] + bias[col], 0.f);
                    o.y = fmaxf(acc[i][j][hh * 2 + 1] + bias[col + 1], 0.f);
                    *reinterpret_cast<float2*>(Cs + rr * CS_P + col) = o;
                }
            }
        }
        __syncthreads();
        float4 wv = *reinterpret_cast<const float4*>(w2 + lane * 4);
        float bias2 = b2[0];
        for (int rr = warp * 16; rr < warp * 16 + 16; rr++) {
            float4 c4 = *reinterpret_cast<const float4*>(Cs + rr * CS_P + lane * 4);
            float p = c4.x * wv.x + c4.y * wv.y + c4.z * wv.z + c4.w * wv.w;
#pragma unroll
            for (int o = 16; o > 0; o >>= 1) p += __shfl_xor_sync(0xffffffffu, p, o);
            int gr = m0 + rr;
            if (lane == 0 && gr < M) outv[gr] = 1.f / (1.f + __expf(-(p + bias2)));
        }
    }
}

// ---------------- dual-weight GEMM: C1 = A@W1+b1, C2 = A@W2+b2 (A staged once) ------
__global__ __launch_bounds__(256, 1)
void mma_gemm2(const float* __restrict__ A, int M,
               const uint32_t* __restrict__ Wf1, const float* __restrict__ b1v, float* __restrict__ C1,
               const uint32_t* __restrict__ Wf2, const float* __restrict__ b2v, float* __restrict__ C2) {
    extern __shared__ uint32_t smem_u[];
    uint32_t* AfH = smem_u;
    uint32_t* AfL = smem_u + 8192;
    uint32_t* BfH = smem_u + 16384;
    uint32_t* BfL = smem_u + 24576;

    int tid = threadIdx.x;
    int m0 = blockIdx.x * 128;
    int warp = tid >> 5, lane = tid & 31;
    int g = lane >> 2, tg = lane & 3;

    copy_Wfrag(BfH, Wf1, tid);
    {
        int r1 = m0 + warp * 16 + g;
        int r2 = r1 + 8;
        const float* p1 = (r1 < M) ? A + (size_t)r1 * H : nullptr;
        const float* p2 = (r2 < M) ? A + (size_t)r2 * H : nullptr;
#pragma unroll 2
        for (int k16i = 0; k16i < 8; k16i++) {
            int k = k16i * 16 + 2 * tg;
            float2 v0a = make_float2(0.f, 0.f), v0b = v0a, v1a = v0a, v1b = v0a;
            if (p1) {
                v0a = *reinterpret_cast<const float2*>(p1 + k);
                v0b = *reinterpret_cast<const float2*>(p1 + k + 8);
            }
            if (p2) {
                v1a = *reinterpret_cast<const float2*>(p2 + k);
                v1b = *reinterpret_cast<const float2*>(p2 + k + 8);
            }
            uint32_t a0h = bf16x2_trunc(v0a.x, v0a.y);
            uint32_t a1h = bf16x2_trunc(v1a.x, v1a.y);
            uint32_t a2h = bf16x2_trunc(v0b.x, v0b.y);
            uint32_t a3h = bf16x2_trunc(v1b.x, v1b.y);
            uint32_t a0l = bf16x2_rn(v0a.x - bf_hi(v0a.x), v0a.y - bf_hi(v0a.y));
            uint32_t a1l = bf16x2_rn(v1a.x - bf_hi(v1a.x), v1a.y - bf_hi(v1a.y));
            uint32_t a2l = bf16x2_rn(v0b.x - bf_hi(v0b.x), v0b.y - bf_hi(v0b.y));
            uint32_t a3l = bf16x2_rn(v1b.x - bf_hi(v1b.x), v1b.y - bf_hi(v1b.y));
            int fi = ((warp * 8 + k16i) * 32 + lane) * 4;
            *reinterpret_cast<uint4*>(AfH + fi) = make_uint4(a0h, a1h, a2h, a3h);
            *reinterpret_cast<uint4*>(AfL + fi) = make_uint4(a0l, a1l, a2l, a3l);
        }
    }
    __syncthreads();

    int wr = warp >> 1, wc = warp & 1;
    float acc[2][8][4];
    mma_mainloop(AfH, AfL, BfH, BfL, wr, wc, lane, acc);
    mma_epi_store(acc, m0, M, wr, wc, g, tg, b1v, 0, C1);

    __syncthreads();   // pass-1 reads of Bf planes complete
    copy_Wfrag(BfH, Wf2, tid);
    __syncthreads();

    mma_mainloop(AfH, AfL, BfH, BfL, wr, wc, lane, acc);
    mma_epi_store(acc, m0, M, wr, wc, g, tg, b2v, 0, C2);
}

// ---------------- small SIMT GEMM for final N=64 decoder layer ----------------
__global__ void gemm64_k(const float* __restrict__ A, int M,
                         const float* __restrict__ W, const float* __restrict__ bias,
                         float* __restrict__ C) {
    __shared__ float As[16][68];
    __shared__ float Ws[16][64];
    int tid = threadIdx.x;
    int m0 = blockIdx.x * 64;
    int ty = tid / 8, tx = tid % 8;

    float acc[4][8];
#pragma unroll
    for (int r = 0; r < 4; r++)
#pragma unroll
        for (int c = 0; c < 8; c++) acc[r][c] = 0.f;

    for (int kk = 0; kk < H; kk += 16) {
        for (int i = tid; i < 256; i += 128) {
            int row = i >> 2, kq = (i & 3) * 4;
            float4 v = make_float4(0.f, 0.f, 0.f, 0.f);
            int gr = m0 + row;
            if (gr < M) v = *reinterpret_cast<const float4*>(A + (size_t)gr * H + kk + kq);
            As[kq + 0][row] = v.x;
            As[kq + 1][row] = v.y;
            As[kq + 2][row] = v.z;
            As[kq + 3][row] = v.w;
        }
        for (int i = tid; i < 256; i += 128) {
            int k = i / 16, cq = (i % 16) * 4;
            *reinterpret_cast<float4*>(&Ws[k][cq]) =
                *reinterpret_cast<const float4*>(W + (size_t)(kk + k) * 64 + cq);
        }
        __syncthreads();
#pragma unroll
        for (int k = 0; k < 16; k++) {
            float4 a4 = *reinterpret_cast<const float4*>(&As[k][ty * 4]);
            float a[4] = {a4.x, a4.y, a4.z, a4.w};
            float4 w0 = *reinterpret_cast<const float4*>(&Ws[k][tx * 8]);
            float4 w1 = *reinterpret_cast<const float4*>(&Ws[k][tx * 8 + 4]);
            float w[8] = {w0.x, w0.y, w0.z, w0.w, w1.x, w1.y, w1.z, w1.w};
#pragma unroll
            for (int r = 0; r < 4; r++)
#pragma unroll
                for (int c = 0; c < 8; c++) acc[r][c] = fmaf(a[r], w[c], acc[r][c]);
        }
        __syncthreads();
    }
#pragma unroll
    for (int r = 0; r < 4; r++) {
        int gr = m0 + ty * 4 + r;
        if (gr < M) {
#pragma unroll
            for (int c = 0; c < 8; c += 4) {
                float4 o;
                o.x = acc[r][c + 0] + bias[tx * 8 + c + 0];
                o.y = acc[r][c + 1] + bias[tx * 8 + c + 1];
                o.z = acc[r][c + 2] + bias[tx * 8 + c + 2];
                o.w = acc[r][c + 3] + bias[tx * 8 + c + 3];
                *reinterpret_cast<float4*>(C + (size_t)gr * 64 + tx * 8 + c) = o;
            }
        }
    }
}

// ---------------- GATv2: one warp per dst, online softmax, unroll-2 ----------------
__device__ __forceinline__ float leaky_dot(float4 l, float4 r, float4 a) {
    float t0 = l.x + r.x; t0 = t0 > 0.f ? t0 : 0.2f * t0;
    float t1 = l.y + r.y; t1 = t1 > 0.f ? t1 : 0.2f * t1;
    float t2 = l.z + r.z; t2 = t2 > 0.f ? t2 : 0.2f * t2;
    float t3 = l.w + r.w; t3 = t3 > 0.f ? t3 : 0.2f * t3;
    return t0 * a.x + t1 * a.y + t2 * a.z + t3 * a.w;
}

__global__ void gat_kernel(const float* __restrict__ xl, const float* __restrict__ xr,
                           const float* __restrict__ att, const float* __restrict__ bias,
                           float* __restrict__ hout) {
    int gw = (blockIdx.x * blockDim.x + threadIdx.x) >> 5;
    if (gw >= NN) return;
    int lane = threadIdx.x & 31;

    const float4* XL = reinterpret_cast<const float4*>(xl);
    float4 r4 = reinterpret_cast<const float4*>(xr)[gw * 32 + lane];
    float4 a4 = reinterpret_cast<const float4*>(att)[lane];

    float4 l4 = XL[gw * 32 + lane];
    float m;
    {
        float p = leaky_dot(l4, r4, a4);
#pragma unroll
        for (int o = 16; o > 0; o >>= 1) p += __shfl_xor_sync(0xffffffffu, p, o);
        m = p;
    }
    float s = 1.f;
    float4 acc = l4;

    int beg = g_off[gw], end = g_off[gw + 1];
    int j = beg;
    float4 vA, vB;
    if (j < end) vA = XL[(size_t)g_csr[j] * 32 + lane];
    if (j + 1 < end) vB = XL[(size_t)g_csr[j + 1] * 32 + lane];

    for (; j + 2 <= end; j += 2) {
        float4 v0 = vA, v1 = vB;
        if (j + 2 < end) vA = XL[(size_t)g_csr[j + 2] * 32 + lane];
        if (j + 3 < end) vB = XL[(size_t)g_csr[j + 3] * 32 + lane];

        float p0 = leaky_dot(v0, r4, a4);
        float p1 = leaky_dot(v1, r4, a4);
#pragma unroll
        for (int o = 16; o > 0; o >>= 1) {
            p0 += __shfl_xor_sync(0xffffffffu, p0, o);
            p1 += __shfl_xor_sync(0xffffffffu, p1, o);
        }
        if (p0 > m) {
            float f = __expf(m - p0);
            s = s * f + 1.f;
            acc.x = acc.x * f + v0.x; acc.y = acc.y * f + v0.y;
            acc.z = acc.z * f + v0.z; acc.w = acc.w * f + v0.w;
            m = p0;
        } else {
            float w = __expf(p0 - m);
            s += w;
            acc.x += v0.x * w; acc.y += v0.y * w;
            acc.z += v0.z * w; acc.w += v0.w * w;
        }
        if (p1 > m) {
            float f = __expf(m - p1);
            s = s * f + 1.f;
            acc.x = acc.x * f + v1.x; acc.y = acc.y * f + v1.y;
            acc.z = acc.z * f + v1.z; acc.w = acc.w * f + v1.w;
            m = p1;
        } else {
            float w = __expf(p1 - m);
            s += w;
            acc.x += v1.x * w; acc.y += v1.y * w;
            acc.z += v1.z * w; acc.w += v1.w * w;
        }
    }
    if (j < end) {
        float4 v0 = vA;
        float p0 = leaky_dot(v0, r4, a4);
#pragma unroll
        for (int o = 16; o > 0; o >>= 1) p0 += __shfl_xor_sync(0xffffffffu, p0, o);
        if (p0 > m) {
            float f = __expf(m - p0);
            s = s * f + 1.f;
            acc.x = acc.x * f + v0.x; acc.y = acc.y * f + v0.y;
            acc.z = acc.z * f + v0.z; acc.w = acc.w * f + v0.w;
            m = p0;
        } else {
            float w = __expf(p0 - m);
            s += w;
            acc.x += v0.x * w; acc.y += v0.y * w;
            acc.z += v0.z * w; acc.w += v0.w * w;
        }
    }

    float inv = 1.f / s;
    float4 b4 = reinterpret_cast<const float4*>(bias)[lane];
    float4 o;
    o.x = acc.x * inv + b4.x;
    o.y = acc.y * inv + b4.y;
    o.z = acc.z * inv + b4.z;
    o.w = acc.w * inv + b4.w;
    reinterpret_cast<float4*>(hout)[gw * 32 + lane] = o;
}

// ---------------- launcher ----------------
extern "C" void kernel_launch(void* const* d_in, const int* in_sizes, int n_in,
                              void* d_out, int out_size) {
    (void)in_sizes; (void)n_in; (void)out_size;
    const float* x    = (const float*)d_in[0];
    const float* emb  = (const float*)d_in[1];
    const int*   eidx = (const int*)d_in[2];
    const int*   blk  = (const int*)d_in[3];
    const int*   eim  = (const int*)d_in[4];
    const float* encW = (const float*)d_in[5];
    const float* encB = (const float*)d_in[6];
    const float* gWl  = (const float*)d_in[7];
    const float* gbl  = (const float*)d_in[8];
    const float* gWr  = (const float*)d_in[9];
    const float* gbr  = (const float*)d_in[10];
    const float* gatt = (const float*)d_in[11];
    const float* gb   = (const float*)d_in[12];
    const float* eW0  = (const float*)d_in[13];
    const float* eb0  = (const float*)d_in[14];
    const float* eW1  = (const float*)d_in[15];
    const float* eb1  = (const float*)d_in[16];
    const float* eW2  = (const float*)d_in[17];
    const float* eb2  = (const float*)d_in[18];
    const float* nW0  = (const float*)d_in[19];
    const float* nb0  = (const float*)d_in[20];
    const float* nW1  = (const float*)d_in[21];
    const float* nb1  = (const float*)d_in[22];
    const float* nW2  = (const float*)d_in[23];
    const float* nb2  = (const float*)d_in[24];
    float* out = (float*)d_out;

    float *pA, *pB, *pL, *pR;
    cudaGetSymbolAddress((void**)&pA, g_A);
    cudaGetSymbolAddress((void**)&pB, g_B);
    cudaGetSymbolAddress((void**)&pL, g_L);
    cudaGetSymbolAddress((void**)&pR, g_R);
    uint32_t* pWf;
    cudaGetSymbolAddress((void**)&pWf, g_Wf);

    cudaFuncSetAttribute(mma_gemm<0, 0>, cudaFuncAttributeMaxDynamicSharedMemorySize, MMA_SMEM_BYTES);
    cudaFuncSetAttribute(mma_gemm<0, 1>, cudaFuncAttributeMaxDynamicSharedMemorySize, MMA_SMEM_BYTES);
    cudaFuncSetAttribute(mma_gemm<1, 1>, cudaFuncAttributeMaxDynamicSharedMemorySize, MMA_SMEM_BYTES);
    cudaFuncSetAttribute(mma_gemm<2, 2>, cudaFuncAttributeMaxDynamicSharedMemorySize, MMA_SMEM_BYTES);
    cudaFuncSetAttribute(mma_gemm<3, 1>, cudaFuncAttributeMaxDynamicSharedMemorySize, MMA_SMEM_BYTES);
    cudaFuncSetAttribute(mma_gemm2,      cudaFuncAttributeMaxDynamicSharedMemorySize, MMA_SMEM_BYTES);

    const int* src = eidx;
    const int* dst = eidx + NE;
    const int* im0 = eim;
    const int* im1 = eim + NI;

    // weight fragment prep (14 matrices)
    prep_weights<<<14, 256>>>(encW, gWl, gWr, eW0, eW1, nW0, nW1);

    // CSR by dst (multi-block scan)
    zero_deg_kernel<<<(NN + 255) / 256, 256>>>();
    count_deg_kernel<<<(NE + 255) / 256, 256>>>(dst);
    scan1_kernel<<<SCAN_NBLK, 256>>>();
    scan2_kernel<<<1, 256>>>();
    scan3_kernel<<<SCAN_NBLK, 256>>>();
    scatter_kernel<<<(NE + 255) / 256, 256>>>(src, dst);

    // encoder MLP (layer 1 stages concat(x|emb) directly)
    int gN = (NN + 127) / 128;
    mma_gemm<3, 1><<<gN, 256, MMA_SMEM_BYTES>>>(x, emb, nullptr, nullptr, NN, pWf + 0 * 16384, encB,         pB, nullptr, nullptr, nullptr);
    mma_gemm<0, 1><<<gN, 256, MMA_SMEM_BYTES>>>(pB, nullptr, nullptr, nullptr, NN, pWf + 1 * 16384, encB + H,     pL, nullptr, nullptr, nullptr);
    mma_gemm<0, 0><<<gN, 256, MMA_SMEM_BYTES>>>(pL, nullptr, nullptr, nullptr, NN, pWf + 2 * 16384, encB + 2 * H, pA, nullptr, nullptr, nullptr);

    // 3 GATv2 layers: xl/xr from one A staging
    float* hcur = pA;
    float* hnxt = pB;
    for (int i = 0; i < 3; i++) {
        mma_gemm2<<<gN, 256, MMA_SMEM_BYTES>>>(hcur, NN,
                                               pWf + (3 + i) * 16384, gbl + i * H, pL,
                                               pWf + (6 + i) * 16384, gbr + i * H, pR);
        gat_kernel<<<(NN * 32 + 255) / 256, 256>>>(pL, pR, gatt + i * H, gb + i * H, hnxt);
        float* t = hcur; hcur = hnxt; hnxt = t;
    }
    // hcur == pB after 3 layers

    // edge decoder: Ha/Hb from one A staging
    mma_gemm2<<<gN, 256, MMA_SMEM_BYTES>>>(hcur, NN, pWf + 9 * 16384, eb0, pL,
                                           pWf + 10 * 16384, nullptr, pR);
    // fused: relu(Ha[s]+Hb[d]) @ W1 + b1 -> relu -> dot W2 + b2 -> sigmoid
    mma_gemm<2, 2><<<(NI + 127) / 128, 256, MMA_SMEM_BYTES>>>(pL, pR, im0, im1, NI, pWf + 11 * 16384, eb1, nullptr, eW2, eb2, out + NB * 64);

    // node decoder on block_index rows
    int gB = (NB + 127) / 128;
    mma_gemm<1, 1><<<gB, 256, MMA_SMEM_BYTES>>>(hcur, nullptr, blk, nullptr, NB, pWf + 12 * 16384, nb0, pL, nullptr, nullptr, nullptr);
    mma_gemm<0, 1><<<gB, 256, MMA_SMEM_BYTES>>>(pL, nullptr, nullptr, nullptr, NB, pWf + 13 * 16384, nb1, pR, nullptr, nullptr, nullptr);
    gemm64_k<<<(NB + 63) / 64, 128>>>(pR, NB, nW2, nb2, out);
}

// round 17
// speedup vs baseline: 1.4523x; 1.4523x over previous
#include <cuda_runtime.h>
#include <math.h>
#include <stdint.h>

#define NN 50000
#define NE 1000000
#define NI 200000
#define NB 5000
#define H  128

#define SCAN_NBLK ((NN + 255) / 256)   // 196

// ---------------- scratch (device globals; no runtime alloc) ----------------
__device__ float g_A[NN * H];
__device__ float g_B[NN * H];
__device__ float g_L[NN * H];
__device__ float g_R[NN * H];
__device__ int   g_deg[NN];
__device__ int   g_off[NN + 1];
__device__ int   g_cur[NN];
__device__ int   g_csr[NE];
__device__ int   g_bsum[SCAN_NBLK];
__device__ int   g_bpre[SCAN_NBLK];
// pre-converted weight fragment planes: 14 matrices x (8192 hi + 8192 lo) words
__device__ uint32_t g_Wf[14 * 16384];

// ---------------- small utility kernels ----------------
__global__ void zero_deg_kernel() {
    int i = blockIdx.x * blockDim.x + threadIdx.x;
    if (i < NN) g_deg[i] = 0;
}

__global__ void count_deg_kernel(const int* __restrict__ dst) {
    int e = blockIdx.x * blockDim.x + threadIdx.x;
    if (e < NE) atomicAdd(&g_deg[dst[e]], 1);
}

// ---- 3-phase multi-block exclusive scan of g_deg -> g_off/g_cur ----
__global__ void scan1_kernel() {
    __shared__ int ts[256];
    int b = blockIdx.x, tid = threadIdx.x;
    int idx = b * 256 + tid;
    int d = (idx < NN) ? g_deg[idx] : 0;
    ts[tid] = d;
    __syncthreads();
#pragma unroll
    for (int o = 1; o < 256; o <<= 1) {
        int t = (tid >= o) ? ts[tid - o] : 0;
        __syncthreads();
        ts[tid] += t;
        __syncthreads();
    }
    if (idx < NN) g_off[idx] = ts[tid] - d;   // local exclusive prefix
    if (tid == 255) g_bsum[b] = ts[255];
}

__global__ void scan2_kernel() {
    __shared__ int ts[256];
    int tid = threadIdx.x;
    int v = (tid < SCAN_NBLK) ? g_bsum[tid] : 0;
    ts[tid] = v;
    __syncthreads();
#pragma unroll
    for (int o = 1; o < 256; o <<= 1) {
        int t = (tid >= o) ? ts[tid - o] : 0;
        __syncthreads();
        ts[tid] += t;
        __syncthreads();
    }
    if (tid < SCAN_NBLK) g_bpre[tid] = ts[tid] - v;   // exclusive block offset
    if (tid == SCAN_NBLK - 1) g_off[NN] = ts[tid];
}

__global__ void scan3_kernel() {
    int b = blockIdx.x, tid = threadIdx.x;
    int idx = b * 256 + tid;
    if (idx < NN) {
        int o = g_off[idx] + g_bpre[b];
        g_off[idx] = o;
        g_cur[idx] = o;
    }
}

__global__ void scatter_kernel(const int* __restrict__ src, const int* __restrict__ dst) {
    int e = blockIdx.x * blockDim.x + threadIdx.x;
    if (e < NE) {
        int d = dst[e];
        int p = atomicAdd(&g_cur[d], 1);
        g_csr[p] = src[e];
    }
}

// ---------------- bf16 split helpers ----------------
__device__ __forceinline__ uint32_t bf16x2_trunc(float x0, float x1) {
    uint32_t r;
    asm("prmt.b32 %0, %1, %2, 0x7632;" : "=r"(r)
        : "r"(__float_as_uint(x0)), "r"(__float_as_uint(x1)));
    return r;
}
__device__ __forceinline__ float bf_hi(float x) {
    return __uint_as_float(__float_as_uint(x) & 0xFFFF0000u);
}
__device__ __forceinline__ uint32_t bf16x2_rn(float x0, float x1) {
    uint32_t r;
    asm("cvt.rn.bf16x2.f32 %0, %1, %2;" : "=r"(r) : "f"(x1), "f"(x0));
    return r;
}

__device__ __forceinline__ void mma_bf16(float* d, const uint32_t* a, const uint32_t* b) {
    asm volatile(
        "mma.sync.aligned.m16n8k16.row.col.f32.bf16.bf16.f32 "
        "{%0,%1,%2,%3}, {%4,%5,%6,%7}, {%8,%9}, {%0,%1,%2,%3};\n"
        : "+f"(d[0]), "+f"(d[1]), "+f"(d[2]), "+f"(d[3])
        : "r"(a[0]), "r"(a[1]), "r"(a[2]), "r"(a[3]), "r"(b[0]), "r"(b[1]));
}

// ---------------- weight prep: convert 14 matrices to fragment planes ----------------
__global__ __launch_bounds__(256)
void prep_weights(const float* __restrict__ encW, const float* __restrict__ gWl,
                  const float* __restrict__ gWr, const float* __restrict__ eW0,
                  const float* __restrict__ eW1, const float* __restrict__ nW0,
                  const float* __restrict__ nW1) {
    int b = blockIdx.x;
    const float* W;
    if (b < 3)       W = encW + b * 16384;
    else if (b < 6)  W = gWl + (b - 3) * 16384;
    else if (b < 9)  W = gWr + (b - 6) * 16384;
    else if (b == 9) W = eW0;
    else if (b == 10) W = eW0 + 16384;
    else if (b == 11) W = eW1;
    else if (b == 12) W = nW0;
    else             W = nW1;
    uint32_t* dstH = g_Wf + b * 16384;
    uint32_t* dstL = dstH + 8192;

    int tid = threadIdx.x;
    int warp = tid >> 5, lane = tid & 31, g = lane >> 2, tg = lane & 3;
#pragma unroll
    for (int h = 0; h < 2; h++) {
        int cbi = warp * 2 + h;
        const float* Wc = W + cbi * 8 + g;
#pragma unroll 2
        for (int k16i = 0; k16i < 8; k16i++) {
            int k = k16i * 16 + 2 * tg;
            float w0 = Wc[(size_t)k * 128];
            float w1 = Wc[(size_t)(k + 1) * 128];
            float w8 = Wc[(size_t)(k + 8) * 128];
            float w9 = Wc[(size_t)(k + 9) * 128];
            uint32_t b0h = bf16x2_trunc(w0, w1);
            uint32_t b1h = bf16x2_trunc(w8, w9);
            uint32_t b0l = bf16x2_rn(w0 - bf_hi(w0), w1 - bf_hi(w1));
            uint32_t b1l = bf16x2_rn(w8 - bf_hi(w8), w9 - bf_hi(w9));
            int fi = ((k16i * 8 + warp) * 32 + lane) * 4 + h * 2;
            *reinterpret_cast<uint2*>(dstH + fi) = make_uint2(b0h, b1h);
            *reinterpret_cast<uint2*>(dstL + fi) = make_uint2(b0l, b1l);
        }
    }
}

// SMEM planes (uint32 words):
//   AfH/AfL: [rbi(8)][k16i(8)][lane(32)][4] = 8192 words each
//   BfH/BfL: [k16i(8)][cbj(8)][lane(32)][4] = 8192 words each (paired cbi)
#define MMA_SMEM_BYTES (32768 * 4)
#define CS_P 132

__device__ __forceinline__ void copy_Wfrag(uint32_t* BfH, const uint32_t* __restrict__ Wf,
                                           int tid) {
    const uint4* s = reinterpret_cast<const uint4*>(Wf);
    uint4* d = reinterpret_cast<uint4*>(BfH);
#pragma unroll 4
    for (int i = tid; i < 4096; i += 256) d[i] = s[i];
}

__device__ __forceinline__ void mma_mainloop(const uint32_t* AfH, const uint32_t* AfL,
                                             const uint32_t* BfH, const uint32_t* BfL,
                                             int wr, int wc, int lane,
                                             float acc[2][8][4]) {
#pragma unroll
    for (int i = 0; i < 2; i++)
#pragma unroll
        for (int j = 0; j < 8; j++)
#pragma unroll
            for (int c = 0; c < 4; c++) acc[i][j][c] = 0.f;

#pragma unroll 2
    for (int k16i = 0; k16i < 8; k16i++) {
        uint4 ah[2], al[2];
#pragma unroll
        for (int i = 0; i < 2; i++) {
            int fi = (((wr * 2 + i) * 8 + k16i) * 32 + lane) * 4;
            ah[i] = *reinterpret_cast<const uint4*>(AfH + fi);
            al[i] = *reinterpret_cast<const uint4*>(AfL + fi);
        }
        uint4 bh[4], bl[4];
#pragma unroll
        for (int p = 0; p < 4; p++) {
            int fi = ((k16i * 8 + wc * 4 + p) * 32 + lane) * 4;
            bh[p] = *reinterpret_cast<const uint4*>(BfH + fi);
            bl[p] = *reinterpret_cast<const uint4*>(BfL + fi);
        }
#pragma unroll
        for (int i = 0; i < 2; i++) {
            uint32_t aH[4] = {ah[i].x, ah[i].y, ah[i].z, ah[i].w};
            uint32_t aL[4] = {al[i].x, al[i].y, al[i].z, al[i].w};
#pragma unroll
            for (int p = 0; p < 4; p++) {
                uint32_t bH0[2] = {bh[p].x, bh[p].y};
                uint32_t bH1[2] = {bh[p].z, bh[p].w};
                uint32_t bL0[2] = {bl[p].x, bl[p].y};
                uint32_t bL1[2] = {bl[p].z, bl[p].w};
                mma_bf16(acc[i][2 * p + 0], aH, bH0);
                mma_bf16(acc[i][2 * p + 0], aH, bL0);
                mma_bf16(acc[i][2 * p + 0], aL, bH0);
                mma_bf16(acc[i][2 * p + 1], aH, bH1);
                mma_bf16(acc[i][2 * p + 1], aH, bL1);
                mma_bf16(acc[i][2 * p + 1], aL, bH1);
            }
        }
    }
}

__device__ __forceinline__ void mma_epi_store(float acc[2][8][4], int m0, int M,
                                              int wr, int wc, int g, int tg,
                                              const float* __restrict__ bias, int relu,
                                              float* __restrict__ C) {
    int rA0 = wr * 32, cB0 = wc * 64;
#pragma unroll
    for (int i = 0; i < 2; i++) {
#pragma unroll
        for (int hh = 0; hh < 2; hh++) {
            int gr = m0 + rA0 + i * 16 + g + hh * 8;
            if (gr < M) {
#pragma unroll
                for (int j = 0; j < 8; j++) {
                    int col = cB0 + j * 8 + 2 * tg;
                    float b0v = bias ? bias[col] : 0.f;
                    float b1v = bias ? bias[col + 1] : 0.f;
                    float2 o;
                    o.x = acc[i][j][hh * 2 + 0] + b0v;
                    o.y = acc[i][j][hh * 2 + 1] + b1v;
                    if (relu) { o.x = fmaxf(o.x, 0.f); o.y = fmaxf(o.y, 0.f); }
                    *reinterpret_cast<float2*>(C + (size_t)gr * 128 + col) = o;
                }
            }
        }
    }
}

// ---------------- split-bf16 GEMM: C[M,128] = epi(A[M,128] @ W + b) ----------------
// MODE_A: 0=plain, 1=gather idx0, 2=relu(Ha[idx0]+Hb[idx1]), 3=concat(x[64]|emb[64])
// MODE_E: 0=bias, 1=bias+relu, 2=fused relu->dot(w2)+b2->sigmoid->outv
template <int MODE_A, int MODE_E>
__global__ __launch_bounds__(256, 1)
void mma_gemm(const float* __restrict__ A, const float* __restrict__ A2,
              const int* __restrict__ idx0, const int* __restrict__ idx1,
              int M, const uint32_t* __restrict__ Wf, const float* __restrict__ bias,
              float* __restrict__ C, const float* __restrict__ w2,
              const float* __restrict__ b2, float* __restrict__ outv) {
    extern __shared__ uint32_t smem_u[];
    uint32_t* AfH = smem_u;
    uint32_t* AfL = smem_u + 8192;
    uint32_t* BfH = smem_u + 16384;
    uint32_t* BfL = smem_u + 24576;

    int tid = threadIdx.x;
    int m0 = blockIdx.x * 128;
    int warp = tid >> 5, lane = tid & 31;
    int g = lane >> 2, tg = lane & 3;

    copy_Wfrag(BfH, Wf, tid);

    // ---- stage A hi/lo fragments: rbi = warp, rows r1 = m0+warp*16+g, r2 = r1+8 ----
    {
        int r1 = m0 + warp * 16 + g;
        int r2 = r1 + 8;
        bool ok1 = r1 < M, ok2 = r2 < M;
        const float *p1 = nullptr, *p2 = nullptr, *q1 = nullptr, *q2 = nullptr;
        if constexpr (MODE_A == 0) {
            if (ok1) p1 = A + (size_t)r1 * H;
            if (ok2) p2 = A + (size_t)r2 * H;
        } else if constexpr (MODE_A == 1) {
            if (ok1) p1 = A + (size_t)__ldg(idx0 + r1) * H;
            if (ok2) p2 = A + (size_t)__ldg(idx0 + r2) * H;
        } else if constexpr (MODE_A == 2) {
            if (ok1) { p1 = A + (size_t)__ldg(idx0 + r1) * H; q1 = A2 + (size_t)__ldg(idx1 + r1) * H; }
            if (ok2) { p2 = A + (size_t)__ldg(idx0 + r2) * H; q2 = A2 + (size_t)__ldg(idx1 + r2) * H; }
        }
#pragma unroll 2
        for (int k16i = 0; k16i < 8; k16i++) {
            int k = k16i * 16 + 2 * tg;
            float2 v0a = make_float2(0.f, 0.f), v0b = v0a, v1a = v0a, v1b = v0a;
            if constexpr (MODE_A == 3) {
                int kk = (k16i < 4) ? k : (k - 64);
                const float* s = (k16i < 4) ? A : A2;
                if (ok1) {
                    v0a = *reinterpret_cast<const float2*>(s + (size_t)r1 * 64 + kk);
                    v0b = *reinterpret_cast<const float2*>(s + (size_t)r1 * 64 + kk + 8);
                }
                if (ok2) {
                    v1a = *reinterpret_cast<const float2*>(s + (size_t)r2 * 64 + kk);
                    v1b = *reinterpret_cast<const float2*>(s + (size_t)r2 * 64 + kk + 8);
                }
            } else if constexpr (MODE_A == 2) {
                if (p1) {
                    float2 a0 = *reinterpret_cast<const float2*>(p1 + k);
                    float2 b0 = *reinterpret_cast<const float2*>(q1 + k);
                    float2 a8 = *reinterpret_cast<const float2*>(p1 + k + 8);
                    float2 b8 = *reinterpret_cast<const float2*>(q1 + k + 8);
                    v0a = make_float2(fmaxf(a0.x + b0.x, 0.f), fmaxf(a0.y + b0.y, 0.f));
                    v0b = make_float2(fmaxf(a8.x + b8.x, 0.f), fmaxf(a8.y + b8.y, 0.f));
                }
                if (p2) {
                    float2 a0 = *reinterpret_cast<const float2*>(p2 + k);
                    float2 b0 = *reinterpret_cast<const float2*>(q2 + k);
                    float2 a8 = *reinterpret_cast<const float2*>(p2 + k + 8);
                    float2 b8 = *reinterpret_cast<const float2*>(q2 + k + 8);
                    v1a = make_float2(fmaxf(a0.x + b0.x, 0.f), fmaxf(a0.y + b0.y, 0.f));
                    v1b = make_float2(fmaxf(a8.x + b8.x, 0.f), fmaxf(a8.y + b8.y, 0.f));
                }
            } else {
                if (p1) {
                    v0a = *reinterpret_cast<const float2*>(p1 + k);
                    v0b = *reinterpret_cast<const float2*>(p1 + k + 8);
                }
                if (p2) {
                    v1a = *reinterpret_cast<const float2*>(p2 + k);
                    v1b = *reinterpret_cast<const float2*>(p2 + k + 8);
                }
            }
            uint32_t a0h = bf16x2_trunc(v0a.x, v0a.y);
            uint32_t a1h = bf16x2_trunc(v1a.x, v1a.y);
            uint32_t a2h = bf16x2_trunc(v0b.x, v0b.y);
            uint32_t a3h = bf16x2_trunc(v1b.x, v1b.y);
            uint32_t a0l = bf16x2_rn(v0a.x - bf_hi(v0a.x), v0a.y - bf_hi(v0a.y));
            uint32_t a1l = bf16x2_rn(v1a.x - bf_hi(v1a.x), v1a.y - bf_hi(v1a.y));
            uint32_t a2l = bf16x2_rn(v0b.x - bf_hi(v0b.x), v0b.y - bf_hi(v0b.y));
            uint32_t a3l = bf16x2_rn(v1b.x - bf_hi(v1b.x), v1b.y - bf_hi(v1b.y));
            int fi = ((warp * 8 + k16i) * 32 + lane) * 4;
            *reinterpret_cast<uint4*>(AfH + fi) = make_uint4(a0h, a1h, a2h, a3h);
            *reinterpret_cast<uint4*>(AfL + fi) = make_uint4(a0l, a1l, a2l, a3l);
        }
    }
    __syncthreads();

    int wr = warp >> 1, wc = warp & 1;
    float acc[2][8][4];
    mma_mainloop(AfH, AfL, BfH, BfL, wr, wc, lane, acc);

    if constexpr (MODE_E < 2) {
        mma_epi_store(acc, m0, M, wr, wc, g, tg, bias, MODE_E == 1, C);
    } else {
        // fused tail: relu(acc + b1) -> Cs(smem) -> dot(w2)+b2 -> sigmoid
        __syncthreads();
        float* Cs = reinterpret_cast<float*>(smem_u);
        int rA0 = wr * 32, cB0 = wc * 64;
#pragma unroll
        for (int i = 0; i < 2; i++) {
#pragma unroll
            for (int hh = 0; hh < 2; hh++) {
                int rr = rA0 + i * 16 + g + hh * 8;
#pragma unroll
                for (int j = 0; j < 8; j++) {
                    int col = cB0 + j * 8 + 2 * tg;
                    float2 o;
                    o.x = fmaxf(acc[i][j][hh * 2 + 0] + bias[col], 0.f);
                    o.y = fmaxf(acc[i][j][hh * 2 + 1] + bias[col + 1], 0.f);
                    *reinterpret_cast<float2*>(Cs + rr * CS_P + col) = o;
                }
            }
        }
        __syncthreads();
        float4 wv = *reinterpret_cast<const float4*>(w2 + lane * 4);
        float bias2 = b2[0];
        for (int rr = warp * 16; rr < warp * 16 + 16; rr++) {
            float4 c4 = *reinterpret_cast<const float4*>(Cs + rr * CS_P + lane * 4);
            float p = c4.x * wv.x + c4.y * wv.y + c4.z * wv.z + c4.w * wv.w;
#pragma unroll
            for (int o = 16; o > 0; o >>= 1) p += __shfl_xor_sync(0xffffffffu, p, o);
            int gr = m0 + rr;
            if (lane == 0 && gr < M) outv[gr] = 1.f / (1.f + __expf(-(p + bias2)));
        }
    }
}

// ---------------- dual-weight GEMM: C1 = A@W1+b1, C2 = A@W2+b2 (A staged once) ------
__global__ __launch_bounds__(256, 1)
void mma_gemm2(const float* __restrict__ A, int M,
               const uint32_t* __restrict__ Wf1, const float* __restrict__ b1v, float* __restrict__ C1,
               const uint32_t* __restrict__ Wf2, const float* __restrict__ b2v, float* __restrict__ C2) {
    extern __shared__ uint32_t smem_u[];
    uint32_t* AfH = smem_u;
    uint32_t* AfL = smem_u + 8192;
    uint32_t* BfH = smem_u + 16384;
    uint32_t* BfL = smem_u + 24576;

    int tid = threadIdx.x;
    int m0 = blockIdx.x * 128;
    int warp = tid >> 5, lane = tid & 31;
    int g = lane >> 2, tg = lane & 3;

    copy_Wfrag(BfH, Wf1, tid);
    {
        int r1 = m0 + warp * 16 + g;
        int r2 = r1 + 8;
        const float* p1 = (r1 < M) ? A + (size_t)r1 * H : nullptr;
        const float* p2 = (r2 < M) ? A + (size_t)r2 * H : nullptr;
#pragma unroll 2
        for (int k16i = 0; k16i < 8; k16i++) {
            int k = k16i * 16 + 2 * tg;
            float2 v0a = make_float2(0.f, 0.f), v0b = v0a, v1a = v0a, v1b = v0a;
            if (p1) {
                v0a = *reinterpret_cast<const float2*>(p1 + k);
                v0b = *reinterpret_cast<const float2*>(p1 + k + 8);
            }
            if (p2) {
                v1a = *reinterpret_cast<const float2*>(p2 + k);
                v1b = *reinterpret_cast<const float2*>(p2 + k + 8);
            }
            uint32_t a0h = bf16x2_trunc(v0a.x, v0a.y);
            uint32_t a1h = bf16x2_trunc(v1a.x, v1a.y);
            uint32_t a2h = bf16x2_trunc(v0b.x, v0b.y);
            uint32_t a3h = bf16x2_trunc(v1b.x, v1b.y);
            uint32_t a0l = bf16x2_rn(v0a.x - bf_hi(v0a.x), v0a.y - bf_hi(v0a.y));
            uint32_t a1l = bf16x2_rn(v1a.x - bf_hi(v1a.x), v1a.y - bf_hi(v1a.y));
            uint32_t a2l = bf16x2_rn(v0b.x - bf_hi(v0b.x), v0b.y - bf_hi(v0b.y));
            uint32_t a3l = bf16x2_rn(v1b.x - bf_hi(v1b.x), v1b.y - bf_hi(v1b.y));
            int fi = ((warp * 8 + k16i) * 32 + lane) * 4;
            *reinterpret_cast<uint4*>(AfH + fi) = make_uint4(a0h, a1h, a2h, a3h);
            *reinterpret_cast<uint4*>(AfL + fi) = make_uint4(a0l, a1l, a2l, a3l);
        }
    }
    __syncthreads();

    int wr = warp >> 1, wc = warp & 1;
    float acc[2][8][4];
    mma_mainloop(AfH, AfL, BfH, BfL, wr, wc, lane, acc);
    mma_epi_store(acc, m0, M, wr, wc, g, tg, b1v, 0, C1);

    __syncthreads();   // pass-1 reads of Bf planes complete
    copy_Wfrag(BfH, Wf2, tid);
    __syncthreads();

    mma_mainloop(AfH, AfL, BfH, BfL, wr, wc, lane, acc);
    mma_epi_store(acc, m0, M, wr, wc, g, tg, b2v, 0, C2);
}

// ---------------- small SIMT GEMM for final N=64 decoder layer ----------------
__global__ void gemm64_k(const float* __restrict__ A, int M,
                         const float* __restrict__ W, const float* __restrict__ bias,
                         float* __restrict__ C) {
    __shared__ float As[16][68];
    __shared__ float Ws[16][64];
    int tid = threadIdx.x;
    int m0 = blockIdx.x * 64;
    int ty = tid / 8, tx = tid % 8;

    float acc[4][8];
#pragma unroll
    for (int r = 0; r < 4; r++)
#pragma unroll
        for (int c = 0; c < 8; c++) acc[r][c] = 0.f;

    for (int kk = 0; kk < H; kk += 16) {
        for (int i = tid; i < 256; i += 128) {
            int row = i >> 2, kq = (i & 3) * 4;
            float4 v = make_float4(0.f, 0.f, 0.f, 0.f);
            int gr = m0 + row;
            if (gr < M) v = *reinterpret_cast<const float4*>(A + (size_t)gr * H + kk + kq);
            As[kq + 0][row] = v.x;
            As[kq + 1][row] = v.y;
            As[kq + 2][row] = v.z;
            As[kq + 3][row] = v.w;
        }
        for (int i = tid; i < 256; i += 128) {
            int k = i / 16, cq = (i % 16) * 4;
            *reinterpret_cast<float4*>(&Ws[k][cq]) =
                *reinterpret_cast<const float4*>(W + (size_t)(kk + k) * 64 + cq);
        }
        __syncthreads();
#pragma unroll
        for (int k = 0; k < 16; k++) {
            float4 a4 = *reinterpret_cast<const float4*>(&As[k][ty * 4]);
            float a[4] = {a4.x, a4.y, a4.z, a4.w};
            float4 w0 = *reinterpret_cast<const float4*>(&Ws[k][tx * 8]);
            float4 w1 = *reinterpret_cast<const float4*>(&Ws[k][tx * 8 + 4]);
            float w[8] = {w0.x, w0.y, w0.z, w0.w, w1.x, w1.y, w1.z, w1.w};
#pragma unroll
            for (int r = 0; r < 4; r++)
#pragma unroll
                for (int c = 0; c < 8; c++) acc[r][c] = fmaf(a[r], w[c], acc[r][c]);
        }
        __syncthreads();
    }
#pragma unroll
    for (int r = 0; r < 4; r++) {
        int gr = m0 + ty * 4 + r;
        if (gr < M) {
#pragma unroll
            for (int c = 0; c < 8; c += 4) {
                float4 o;
                o.x = acc[r][c + 0] + bias[tx * 8 + c + 0];
                o.y = acc[r][c + 1] + bias[tx * 8 + c + 1];
                o.z = acc[r][c + 2] + bias[tx * 8 + c + 2];
                o.w = acc[r][c + 3] + bias[tx * 8 + c + 3];
                *reinterpret_cast<float4*>(C + (size_t)gr * 64 + tx * 8 + c) = o;
            }
        }
    }
}

// ---------------- GATv2: one warp per dst, online softmax, unroll-2 ----------------
__device__ __forceinline__ float leaky_dot(float4 l, float4 r, float4 a) {
    float t0 = l.x + r.x; t0 = t0 > 0.f ? t0 : 0.2f * t0;
    float t1 = l.y + r.y; t1 = t1 > 0.f ? t1 : 0.2f * t1;
    float t2 = l.z + r.z; t2 = t2 > 0.f ? t2 : 0.2f * t2;
    float t3 = l.w + r.w; t3 = t3 > 0.f ? t3 : 0.2f * t3;
    return t0 * a.x + t1 * a.y + t2 * a.z + t3 * a.w;
}

__global__ void gat_kernel(const float* __restrict__ xl, const float* __restrict__ xr,
                           const float* __restrict__ att, const float* __restrict__ bias,
                           float* __restrict__ hout) {
    int gw = (blockIdx.x * blockDim.x + threadIdx.x) >> 5;
    if (gw >= NN) return;
    int lane = threadIdx.x & 31;

    const float4* XL = reinterpret_cast<const float4*>(xl);
    float4 r4 = reinterpret_cast<const float4*>(xr)[gw * 32 + lane];
    float4 a4 = reinterpret_cast<const float4*>(att)[lane];

    float4 l4 = XL[gw * 32 + lane];
    float m;
    {
        float p = leaky_dot(l4, r4, a4);
#pragma unroll
        for (int o = 16; o > 0; o >>= 1) p += __shfl_xor_sync(0xffffffffu, p, o);
        m = p;
    }
    float s = 1.f;
    float4 acc = l4;

    int beg = __ldg(g_off + gw), end = __ldg(g_off + gw + 1);
    int j = beg;
    float4 vA, vB;
    if (j < end) vA = XL[(size_t)__ldg(g_csr + j) * 32 + lane];
    if (j + 1 < end) vB = XL[(size_t)__ldg(g_csr + j + 1) * 32 + lane];

    for (; j + 2 <= end; j += 2) {
        float4 v0 = vA, v1 = vB;
        if (j + 2 < end) vA = XL[(size_t)__ldg(g_csr + j + 2) * 32 + lane];
        if (j + 3 < end) vB = XL[(size_t)__ldg(g_csr + j + 3) * 32 + lane];

        float p0 = leaky_dot(v0, r4, a4);
        float p1 = leaky_dot(v1, r4, a4);
#pragma unroll
        for (int o = 16; o > 0; o >>= 1) {
            p0 += __shfl_xor_sync(0xffffffffu, p0, o);
            p1 += __shfl_xor_sync(0xffffffffu, p1, o);
        }
        if (p0 > m) {
            float f = __expf(m - p0);
            s = s * f + 1.f;
            acc.x = acc.x * f + v0.x; acc.y = acc.y * f + v0.y;
            acc.z = acc.z * f + v0.z; acc.w = acc.w * f + v0.w;
            m = p0;
        } else {
            float w = __expf(p0 - m);
            s += w;
            acc.x += v0.x * w; acc.y += v0.y * w;
            acc.z += v0.z * w; acc.w += v0.w * w;
        }
        if (p1 > m) {
            float f = __expf(m - p1);
            s = s * f + 1.f;
            acc.x = acc.x * f + v1.x; acc.y = acc.y * f + v1.y;
            acc.z = acc.z * f + v1.z; acc.w = acc.w * f + v1.w;
            m = p1;
        } else {
            float w = __expf(p1 - m);
            s += w;
            acc.x += v1.x * w; acc.y += v1.y * w;
            acc.z += v1.z * w; acc.w += v1.w * w;
        }
    }
    if (j < end) {
        float4 v0 = vA;
        float p0 = leaky_dot(v0, r4, a4);
#pragma unroll
        for (int o = 16; o > 0; o >>= 1) p0 += __shfl_xor_sync(0xffffffffu, p0, o);
        if (p0 > m) {
            float f = __expf(m - p0);
            s = s * f + 1.f;
            acc.x = acc.x * f + v0.x; acc.y = acc.y * f + v0.y;
            acc.z = acc.z * f + v0.z; acc.w = acc.w * f + v0.w;
            m = p0;
        } else {
            float w = __expf(p0 - m);
            s += w;
            acc.x += v0.x * w; acc.y += v0.y * w;
            acc.z += v0.z * w; acc.w += v0.w * w;
        }
    }

    float inv = 1.f / s;
    float4 b4 = reinterpret_cast<const float4*>(bias)[lane];
    float4 o;
    o.x = acc.x * inv + b4.x;
    o.y = acc.y * inv + b4.y;
    o.z = acc.z * inv + b4.z;
    o.w = acc.w * inv + b4.w;
    reinterpret_cast<float4*>(hout)[gw * 32 + lane] = o;
}

// ---------------- launcher ----------------
extern "C" void kernel_launch(void* const* d_in, const int* in_sizes, int n_in,
                              void* d_out, int out_size) {
    (void)in_sizes; (void)n_in; (void)out_size;
    const float* x    = (const float*)d_in[0];
    const float* emb  = (const float*)d_in[1];
    const int*   eidx = (const int*)d_in[2];
    const int*   blk  = (const int*)d_in[3];
    const int*   eim  = (const int*)d_in[4];
    const float* encW = (const float*)d_in[5];
    const float* encB = (const float*)d_in[6];
    const float* gWl  = (const float*)d_in[7];
    const float* gbl  = (const float*)d_in[8];
    const float* gWr  = (const float*)d_in[9];
    const float* gbr  = (const float*)d_in[10];
    const float* gatt = (const float*)d_in[11];
    const float* gb   = (const float*)d_in[12];
    const float* eW0  = (const float*)d_in[13];
    const float* eb0  = (const float*)d_in[14];
    const float* eW1  = (const float*)d_in[15];
    const float* eb1  = (const float*)d_in[16];
    const float* eW2  = (const float*)d_in[17];
    const float* eb2  = (const float*)d_in[18];
    const float* nW0  = (const float*)d_in[19];
    const float* nb0  = (const float*)d_in[20];
    const float* nW1  = (const float*)d_in[21];
    const float* nb1  = (const float*)d_in[22];
    const float* nW2  = (const float*)d_in[23];
    const float* nb2  = (const float*)d_in[24];
    float* out = (float*)d_out;

    float *pA, *pB, *pL, *pR;
    cudaGetSymbolAddress((void**)&pA, g_A);
    cudaGetSymbolAddress((void**)&pB, g_B);
    cudaGetSymbolAddress((void**)&pL, g_L);
    cudaGetSymbolAddress((void**)&pR, g_R);
    uint32_t* pWf;
    cudaGetSymbolAddress((void**)&pWf, g_Wf);

    cudaFuncSetAttribute(mma_gemm<0, 0>, cudaFuncAttributeMaxDynamicSharedMemorySize, MMA_SMEM_BYTES);
    cudaFuncSetAttribute(mma_gemm<0, 1>, cudaFuncAttributeMaxDynamicSharedMemorySize, MMA_SMEM_BYTES);
    cudaFuncSetAttribute(mma_gemm<1, 1>, cudaFuncAttributeMaxDynamicSharedMemorySize, MMA_SMEM_BYTES);
    cudaFuncSetAttribute(mma_gemm<2, 2>, cudaFuncAttributeMaxDynamicSharedMemorySize, MMA_SMEM_BYTES);
    cudaFuncSetAttribute(mma_gemm<3, 1>, cudaFuncAttributeMaxDynamicSharedMemorySize, MMA_SMEM_BYTES);
    cudaFuncSetAttribute(mma_gemm2,      cudaFuncAttributeMaxDynamicSharedMemorySize, MMA_SMEM_BYTES);

    const int* src = eidx;
    const int* dst = eidx + NE;
    const int* im0 = eim;
    const int* im1 = eim + NI;

    // weight fragment prep (14 matrices)
    prep_weights<<<14, 256>>>(encW, gWl, gWr, eW0, eW1, nW0, nW1);

    // CSR by dst (multi-block scan)
    zero_deg_kernel<<<(NN + 511) / 512, 512>>>();
    count_deg_kernel<<<(NE + 511) / 512, 512>>>(dst);
    scan1_kernel<<<SCAN_NBLK, 256>>>();
    scan2_kernel<<<1, 256>>>();
    scan3_kernel<<<SCAN_NBLK, 256>>>();
    scatter_kernel<<<(NE + 511) / 512, 512>>>(src, dst);

    // encoder MLP (layer 1 stages concat(x|emb) directly)
    int gN = (NN + 127) / 128;
    mma_gemm<3, 1><<<gN, 256, MMA_SMEM_BYTES>>>(x, emb, nullptr, nullptr, NN, pWf + 0 * 16384, encB,         pB, nullptr, nullptr, nullptr);
    mma_gemm<0, 1><<<gN, 256, MMA_SMEM_BYTES>>>(pB, nullptr, nullptr, nullptr, NN, pWf + 1 * 16384, encB + H,     pL, nullptr, nullptr, nullptr);
    mma_gemm<0, 0><<<gN, 256, MMA_SMEM_BYTES>>>(pL, nullptr, nullptr, nullptr, NN, pWf + 2 * 16384, encB + 2 * H, pA, nullptr, nullptr, nullptr);

    // 3 GATv2 layers: xl/xr from one A staging
    float* hcur = pA;
    float* hnxt = pB;
    for (int i = 0; i < 3; i++) {
        mma_gemm2<<<gN, 256, MMA_SMEM_BYTES>>>(hcur, NN,
                                               pWf + (3 + i) * 16384, gbl + i * H, pL,
                                               pWf + (6 + i) * 16384, gbr + i * H, pR);
        gat_kernel<<<(NN * 32 + 255) / 256, 256>>>(pL, pR, gatt + i * H, gb + i * H, hnxt);
        float* t = hcur; hcur = hnxt; hnxt = t;
    }
    // hcur == pB after 3 layers

    // edge decoder: Ha/Hb from one A staging
    mma_gemm2<<<gN, 256, MMA_SMEM_BYTES>>>(hcur, NN, pWf + 9 * 16384, eb0, pL,
                                           pWf + 10 * 16384, nullptr, pR);
    // fused: relu(Ha[s]+Hb[d]) @ W1 + b1 -> relu -> dot W2 + b2 -> sigmoid
    mma_gemm<2, 2><<<(NI + 127) / 128, 256, MMA_SMEM_BYTES>>>(pL, pR, im0, im1, NI, pWf + 11 * 16384, eb1, nullptr, eW2, eb2, out + NB * 64);

    // node decoder on block_index rows
    int gB = (NB + 127) / 128;
    mma_gemm<1, 1><<<gB, 256, MMA_SMEM_BYTES>>>(hcur, nullptr, blk, nullptr, NB, pWf + 12 * 16384, nb0, pL, nullptr, nullptr, nullptr);
    mma_gemm<0, 1><<<gB, 256, MMA_SMEM_BYTES>>>(pL, nullptr, nullptr, nullptr, NB, pWf + 13 * 16384, nb1, pR, nullptr, nullptr, nullptr);
    gemm64_k<<<(NB + 63) / 64, 128>>>(pR, NB, nW2, nb2, out);
}